// round 5
// baseline (speedup 1.0000x reference)
#include <cuda_runtime.h>
#include <math.h>
#include <stdint.h>

// GNN on complete per-scene digraphs: B=64 scenes, N=128 nodes.
// segment_mean at node d = (scene_sum(h) - h[d]) / 127.
// R5: 2-CTA cluster/scene, 512 thr/CTA (8 thr/node).
//  - out = relu(b + cs@Ws - s@Ws); base = b + bp_local + bp_peer (overlap trick)
//  - node-term GEMV uses packed fma.rn.f32x2 (half the FMA instructions)
//  - next layer's colsum fused into emit: warp butterfly + smem atomicAdd
//    (removes the per-layer colsum pass and 2 barriers per layer)

#define NODES    128
#define LOCALN   64
#define SCENES   64
#define THREADS  512
#define STRIDE   77
#define INV127   (1.0f/127.0f)

typedef unsigned long long u64;

// smem layout (floats)
#define S_W1s    0           // 5*64   (W1/127)
#define S_W1s128 320         // 5*64   (W1*128/127)
#define S_B1     640         // 64
#define S_W2s    704         // 75*64
#define S_B2     5504        // 64
#define S_W3s    5568        // 64*32
#define S_B3     7616        // 32
#define S_W4s    7648        // 32*16
#define S_B4     8160        // 16
#define S_WNs    8176        // 16*2
#define S_BN     8208        // 2 (+2)
#define S_WG1    8212        // 16*8
#define S_BG1    8340        // 8
#define S_WG2    8348        // 8
#define S_BG2    8356        // 1 (+3)
#define S_A      8360        // 64*77
#define S_BUF    (S_A + LOCALN*STRIDE)     // 13288
#define S_SLOTA  (S_BUF + LOCALN*STRIDE)   // 18216: csl slot A (80) [64..74]=info sums
#define S_SLOTB  (S_SLOTA + 80)            // 18296: csl slot B (80)
#define S_BP     (S_SLOTB + 80)            // 18376: 2 slots x 64 base-partials
#define S_BASE   (S_BP + 128)              // 18504: 64
#define S_PART   (S_BASE + 64)             // 18568: 176 (info colsum partials)
#define S_TOT    (S_PART + 176)            // 18744
#define SMEM_BYTES (S_TOT * 4)             // 74976 B

__device__ __forceinline__ uint32_t smem_u32(const void* p) {
    uint32_t a;
    asm("{ .reg .u64 t; cvta.to.shared.u64 t, %1; cvt.u32.u64 %0, t; }"
        : "=r"(a) : "l"(p));
    return a;
}
__device__ __forceinline__ float ld_peer_f32(uint32_t local_addr, uint32_t peer_rank) {
    uint32_t remote;
    asm("mapa.shared::cluster.u32 %0, %1, %2;"
        : "=r"(remote) : "r"(local_addr), "r"(peer_rank));
    float v;
    asm volatile("ld.shared::cluster.f32 %0, [%1];" : "=f"(v) : "r"(remote));
    return v;
}
#define CLUSTER_ARRIVE() asm volatile("barrier.cluster.arrive.aligned;" ::: "memory")
#define CLUSTER_WAIT()   asm volatile("barrier.cluster.wait.aligned;"   ::: "memory")

// ---- packed f32x2 helpers ----
__device__ __forceinline__ u64 pack2(float lo, float hi) {
    u64 r; asm("mov.b64 %0, {%1, %2};" : "=l"(r) : "f"(lo), "f"(hi)); return r;
}
__device__ __forceinline__ void unpack2(u64 v, float& lo, float& hi) {
    asm("mov.b64 {%0, %1}, %2;" : "=f"(lo), "=f"(hi) : "l"(v));
}
__device__ __forceinline__ u64 add2(u64 a, u64 b) {
    u64 r; asm("add.rn.f32x2 %0, %1, %2;" : "=l"(r) : "l"(a), "l"(b)); return r;
}
__device__ __forceinline__ u64 fma2(u64 a, u64 b, u64 c) {
    u64 r; asm("fma.rn.f32x2 %0, %1, %2, %3;" : "=l"(r) : "l"(a), "l"(b), "l"(c)); return r;
}

// base-partial: bp[j] = sum_k csl[k] * Ws[k*OUT+j], 4 threads per j.
template<int OUT, int IN>
__device__ __forceinline__ void basepart(const float* __restrict__ csl,
                                         const float* __restrict__ Ws,
                                         float* __restrict__ bp, int tid) {
    if (tid < 4 * OUT) {
        const int j = tid >> 2, p = tid & 3;
        float s = 0.f;
        for (int k = p; k < IN; k += 4) s += csl[k] * Ws[k * OUT + j];
        const unsigned m = (4 * OUT >= 32) ? 0xffffffffu : ((1u << (4 * OUT)) - 1u);
        s += __shfl_xor_sync(m, s, 1);
        s += __shfl_xor_sync(m, s, 2);
        if (p == 0) bp[j] = s;
    }
}

// packed node term: acc2[v] accumulates columns (j0+2v, j0+2v+1)
template<int IN, int OUT, int JT>
__device__ __forceinline__ void nodeterm2(const float* __restrict__ S, int off,
                                          const float* __restrict__ Ws,
                                          u64* __restrict__ acc2, int n, int q) {
    const int j0 = q * JT;
    #pragma unroll
    for (int v = 0; v < JT / 2; v++) acc2[v] = 0ull;
    const float* srow = S + n * STRIDE + off;
    for (int k = 0; k < IN; k++) {
        float a = srow[k];
        u64 aa = pack2(a, a);
        if constexpr (JT == 8) {
            const ulonglong2* wr = reinterpret_cast<const ulonglong2*>(Ws + k * OUT + j0);
            ulonglong2 w0 = wr[0], w1 = wr[1];
            acc2[0] = fma2(aa, w0.x, acc2[0]);
            acc2[1] = fma2(aa, w0.y, acc2[1]);
            acc2[2] = fma2(aa, w1.x, acc2[2]);
            acc2[3] = fma2(aa, w1.y, acc2[3]);
        } else if constexpr (JT == 4) {
            const ulonglong2* wr = reinterpret_cast<const ulonglong2*>(Ws + k * OUT + j0);
            ulonglong2 w0 = wr[0];
            acc2[0] = fma2(aa, w0.x, acc2[0]);
            acc2[1] = fma2(aa, w0.y, acc2[1]);
        } else {
            const u64* wr = reinterpret_cast<const u64*>(Ws + k * OUT + j0);
            acc2[0] = fma2(aa, wr[0], acc2[0]);
        }
    }
}

// emit + fused colsum: r = relu(base - acc); store row; butterfly-reduce r over
// the warp's 32 nodes; lanes 0..JT-1 atomicAdd into csl_next.
template<int JT>
__device__ __forceinline__ void emit_reduce(float* __restrict__ D,
                                            const float* __restrict__ base,
                                            const u64* __restrict__ acc2,
                                            float* __restrict__ csl_next,
                                            int n, int q, int lane) {
    const int j0 = q * JT;
    float* drow = D + n * STRIDE + j0;
    u64 red[JT / 2];
    #pragma unroll
    for (int v = 0; v < JT / 2; v++) {
        float lo, hi;
        unpack2(acc2[v], lo, hi);
        float r0 = fmaxf(base[j0 + 2 * v]     - lo, 0.f);
        float r1 = fmaxf(base[j0 + 2 * v + 1] - hi, 0.f);
        drow[2 * v]     = r0;
        drow[2 * v + 1] = r1;
        red[v] = pack2(r0, r1);
    }
    #pragma unroll
    for (int off = 1; off < 32; off <<= 1) {
        #pragma unroll
        for (int v = 0; v < JT / 2; v++)
            red[v] = add2(red[v], __shfl_xor_sync(0xffffffffu, red[v], off));
    }
    if (lane < JT) {
        float lo, hi;
        unpack2(red[lane >> 1], lo, hi);
        atomicAdd(&csl_next[j0 + lane], (lane & 1) ? hi : lo);
    }
}

__global__ __launch_bounds__(THREADS, 1) __cluster_dims__(2, 1, 1)
void gnn_scene_kernel(const float* __restrict__ obj_info,
                      const float* __restrict__ W1, const float* __restrict__ b1,
                      const float* __restrict__ W2, const float* __restrict__ b2,
                      const float* __restrict__ W3, const float* __restrict__ b3,
                      const float* __restrict__ W4, const float* __restrict__ b4,
                      const float* __restrict__ Wn, const float* __restrict__ bn,
                      const float* __restrict__ Wg1, const float* __restrict__ bg1,
                      const float* __restrict__ Wg2, const float* __restrict__ bg2,
                      float* __restrict__ out) {
    extern __shared__ float sm[];
    const int tid  = threadIdx.x;
    const int lane = tid & 31;
    const int b    = blockIdx.x >> 1;
    const uint32_t rank = blockIdx.x & 1;
    const uint32_t peer = rank ^ 1u;
    const int n = tid & (LOCALN - 1);   // local node 0..63
    const int q = tid >> 6;             // 0..7
    const uint32_t smbase = smem_u32(sm);

    // ---- load + prescale weights ----
    for (int i = tid; i < 5 * 64; i += THREADS) {
        float w = W1[i];
        sm[S_W1s + i]    = w * INV127;
        sm[S_W1s128 + i] = w * (128.0f * INV127);
    }
    #define CPYS(dst, src, cnt) \
        for (int i = tid; i < (cnt); i += THREADS) sm[(dst) + i] = src[i] * INV127;
    #define CPY(dst, src, cnt) \
        for (int i = tid; i < (cnt); i += THREADS) sm[(dst) + i] = src[i];
    CPYS(S_W2s, W2, 75*64);  CPY(S_B2, b2, 64);
    CPYS(S_W3s, W3, 64*32);  CPY(S_B3, b3, 32);
    CPYS(S_W4s, W4, 32*16);  CPY(S_B4, b4, 16);
    CPYS(S_WNs, Wn, 16*2);   CPY(S_BN, bn, 2);
    CPY(S_B1, b1, 64);
    CPY(S_WG1, Wg1, 16*8);   CPY(S_BG1, bg1, 8);
    CPY(S_WG2, Wg2, 8);      CPY(S_BG2, bg2, 1);
    #undef CPYS
    #undef CPY

    // ---- load this CTA's 64 rows of info[b] into A cols 64..74 ----
    {
        const float* src = obj_info + ((size_t)b * NODES + rank * LOCALN) * 11;
        for (int i = tid; i < LOCALN * 11; i += THREADS) {
            int r = i / 11, c = i % 11;
            sm[S_A + r * STRIDE + 64 + c] = src[i];
        }
    }
    // zero csl accumulation slots
    if (tid < 64) { sm[S_SLOTA + tid] = 0.f; sm[S_SLOTB + tid] = 0.f; }
    __syncthreads();

    float* A     = sm + S_A;
    float* Bb    = sm + S_BUF;
    float* slotA = sm + S_SLOTA;
    float* slotB = sm + S_SLOTB;
    float* base  = sm + S_BASE;
    float* part  = sm + S_PART;

    // ---- info colsum (11 cols x 64 rows) -> slotA[64..74] ----
    if (tid < 11 * 16) {
        int c = tid % 11, p = tid / 11;
        float s = 0.f;
        #pragma unroll
        for (int r = 0; r < 4; r++) s += A[(p * 4 + r) * STRIDE + 64 + c];
        part[p * 11 + c] = s;
    }
    __syncthreads();
    if (tid < 11) {
        float s = 0.f;
        #pragma unroll
        for (int p = 0; p < 16; p++) s += part[p * 11 + tid];
        slotA[64 + tid] = s;
    }
    __syncthreads();

    u64 acc2[4];

    // ============ layer 1 (edge): info[:, :5] -> h1 (A cols 0..63) ============
    {
        float* bp = sm + S_BP + 0 * 64;
        basepart<64, 5>(slotA + 64, sm + S_W1s, bp, tid);
        CLUSTER_ARRIVE();
        nodeterm2<5, 64, 8>(A, 64, sm + S_W1s128, acc2, n, q);
        CLUSTER_WAIT();
        if (tid < 64) {
            uint32_t la = smbase + (uint32_t)(S_BP + 0 * 64 + tid) * 4u;
            base[tid] = sm[S_B1 + tid] + bp[tid] + ld_peer_f32(la, peer);
        }
        __syncthreads();
        emit_reduce<8>(A, base, acc2, slotA, n, q, lane);   // csl for L2 -> slotA[0..63]
        __syncthreads();
    }

    // ============ layer 2: h75 (A, cols 0..74; csl=slotA[0..74]) -> h2 (Bb) ============
    {
        float* bp = sm + S_BP + 1 * 64;
        basepart<64, 75>(slotA, sm + S_W2s, bp, tid);
        CLUSTER_ARRIVE();
        nodeterm2<75, 64, 8>(A, 0, sm + S_W2s, acc2, n, q);
        CLUSTER_WAIT();
        if (tid < 64) {
            uint32_t la = smbase + (uint32_t)(S_BP + 1 * 64 + tid) * 4u;
            base[tid] = sm[S_B2 + tid] + bp[tid] + ld_peer_f32(la, peer);
        } else if (tid >= 128 && tid < 192) {
            slotA[tid - 128] = 0.f;     // retire slotA[0..63] for reuse by emit_3
        }
        __syncthreads();
        emit_reduce<8>(Bb, base, acc2, slotB, n, q, lane);  // csl for L3 -> slotB[0..63]
        __syncthreads();
    }

    // ============ layer 3: h2 (Bb; csl=slotB) -> h3 (A cols 0..31) ============
    {
        float* bp = sm + S_BP + 0 * 64;
        basepart<32, 64>(slotB, sm + S_W3s, bp, tid);
        CLUSTER_ARRIVE();
        nodeterm2<64, 32, 4>(Bb, 0, sm + S_W3s, acc2, n, q);
        CLUSTER_WAIT();
        if (tid < 32) {
            uint32_t la = smbase + (uint32_t)(S_BP + 0 * 64 + tid) * 4u;
            base[tid] = sm[S_B3 + tid] + bp[tid] + ld_peer_f32(la, peer);
        } else if (tid >= 128 && tid < 144) {
            slotB[tid - 128] = 0.f;     // retire slotB[0..15] for reuse by emit_4
        }
        __syncthreads();
        emit_reduce<4>(A, base, acc2, slotA, n, q, lane);   // csl for L4 -> slotA[0..31]
        __syncthreads();
    }

    // ============ layer 4: h3 (A cols 0..31; csl=slotA) -> h4 (Bb cols 0..15) ============
    {
        float* bp = sm + S_BP + 1 * 64;
        basepart<16, 32>(slotA, sm + S_W4s, bp, tid);
        CLUSTER_ARRIVE();
        nodeterm2<32, 16, 2>(A, 0, sm + S_W4s, acc2, n, q);
        CLUSTER_WAIT();
        if (tid < 16) {
            uint32_t la = smbase + (uint32_t)(S_BP + 1 * 64 + tid) * 4u;
            base[tid] = sm[S_B4 + tid] + bp[tid] + ld_peer_f32(la, peer);
        }
        __syncthreads();
        emit_reduce<2>(Bb, base, acc2, slotB, n, q, lane);  // csl for heads -> slotB[0..15]
        __syncthreads();
    }

    // ============ node + scene heads on h4 (Bb cols 0..15; csl=slotB) ============
    {
        float* bp = sm + S_BP + 0 * 64;
        basepart<2, 16>(slotB, sm + S_WNs, bp, tid);
        CLUSTER_ARRIVE();
        float accn = 0.f;
        if (q < 2) {
            const float* srow = Bb + n * STRIDE;
            #pragma unroll
            for (int k = 0; k < 16; k++) accn += srow[k] * sm[S_WNs + k * 2 + q];
        }
        CLUSTER_WAIT();
        if (tid < 2) {
            uint32_t la = smbase + (uint32_t)(S_BP + 0 * 64 + tid) * 4u;
            base[tid] = sm[S_BN + tid] + bp[tid] + ld_peer_f32(la, peer);
        }
        __syncthreads();
        if (q < 2) {
            size_t gnode = (size_t)b * NODES + rank * LOCALN + n;
            out[64 + gnode * 2 + q] = base[q] - accn;
        }

        // scene classifier: rank 0 thread 0; cs16 = slotB + peer slotB
        if (rank == 0 && tid == 0) {
            float scene[16];
            #pragma unroll
            for (int k = 0; k < 16; k++) {
                uint32_t la = smbase + (uint32_t)(S_SLOTB + k) * 4u;
                scene[k] = (slotB[k] + ld_peer_f32(la, peer)) * (1.0f / NODES);
            }
            float z = sm[S_BG2];
            #pragma unroll
            for (int o = 0; o < 8; o++) {
                float g = sm[S_BG1 + o];
                #pragma unroll
                for (int k = 0; k < 16; k++) g += scene[k] * sm[S_WG1 + k * 8 + o];
                g = fmaxf(g, 0.f);
                z += g * sm[S_WG2 + o];
            }
            out[b] = 1.0f / (1.0f + expf(-z));
        }
    }

    // protect peer's outstanding DSMEM reads before exit
    CLUSTER_ARRIVE();
    CLUSTER_WAIT();
}

extern "C" void kernel_launch(void* const* d_in, const int* in_sizes, int n_in,
                              void* d_out, int out_size) {
    const float* obj = (const float*)d_in[0];
    const float* W1  = (const float*)d_in[1];
    const float* b1  = (const float*)d_in[2];
    const float* W2  = (const float*)d_in[3];
    const float* b2  = (const float*)d_in[4];
    const float* W3  = (const float*)d_in[5];
    const float* b3  = (const float*)d_in[6];
    const float* W4  = (const float*)d_in[7];
    const float* b4  = (const float*)d_in[8];
    const float* Wn  = (const float*)d_in[9];
    const float* bn  = (const float*)d_in[10];
    const float* Wg1 = (const float*)d_in[11];
    const float* bg1 = (const float*)d_in[12];
    const float* Wg2 = (const float*)d_in[13];
    const float* bg2 = (const float*)d_in[14];
    // d_in[15]=src, d_in[16]=dst: complete graph, exploited analytically.

    cudaFuncSetAttribute(gnn_scene_kernel,
                         cudaFuncAttributeMaxDynamicSharedMemorySize, SMEM_BYTES);
    gnn_scene_kernel<<<SCENES * 2, THREADS, SMEM_BYTES>>>(
        obj, W1, b1, W2, b2, W3, b3, W4, b4, Wn, bn, Wg1, bg1, Wg2, bg2,
        (float*)d_out);
}

// round 6
// speedup vs baseline: 1.0015x; 1.0015x over previous
#include <cuda_runtime.h>
#include <math.h>
#include <stdint.h>

// GNN on complete per-scene digraphs: B=64 scenes, N=128 nodes.
// segment_mean at node d = (scene_sum(h) - h[d]) / 127.
// R6: 2-CTA cluster/scene, 512 thr/CTA (8 thr/node).
//  - out = relu(b + cs@Ws - s@Ws); base = b + bp_local + bp_peer
//  - cross-CTA bp exchange: push (st.shared::cluster) + mbarrier arrive/wait
//    (replaces 490cy cluster barrier + 215cy DSMEM pull per layer)
//  - node-term GEMV in packed fma.rn.f32x2
//  - colsum fused into emit: scalar butterfly, lane0 static-unrolled atomics
//  - 2 __syncthreads per layer

#define NODES    128
#define LOCALN   64
#define SCENES   64
#define THREADS  512
#define STRIDE   77
#define INV127   (1.0f/127.0f)

typedef unsigned long long u64;

// smem layout (float indices)
#define S_W1s    0            // 5*64  (W1/127)
#define S_W1s128 320          // 5*64  (W1*128/127)
#define S_B1     640          // 64
#define S_W2s    704          // 75*64
#define S_B2     5504         // 64
#define S_W3s    5568         // 64*32
#define S_B3     7616         // 32
#define S_W4s    7648         // 32*16
#define S_B4     8160         // 16
#define S_WNs    8176         // 16*2
#define S_BN     8208         // 2 (+2)
#define S_WG1    8212         // 16*8
#define S_BG1    8340         // 8
#define S_WG2    8348         // 8
#define S_BG2    8356         // 1 (+3)
#define S_A      8360         // 64*77
#define S_BUF    13288        // 64*77
#define S_CS2    18216        // 80: [0..63]=h1 csl (atomics), [64..74]=info csl
#define S_CS3    18296        // 64
#define S_CS4    18360        // 32
#define S_CS5    18392        // 16
#define S_BASE   18408        // 64
#define S_BPP1   18472        // 64  peer bp, layer 1
#define S_BPP2   18536        // 64
#define S_BPP3   18600        // 32
#define S_BPP4   18632        // 16
#define S_BPPH   18648        // 2 (+2)
#define S_SCENEB 18652        // 16
#define S_PART   18668        // 176 (info colsum partials)
#define S_MBAR   18844        // 6 mbarriers x 2 floats (8B aligned)
#define S_TOT    18856
#define SMEM_BYTES (S_TOT * 4)   // 75424 B

__device__ __forceinline__ uint32_t smem_u32(const void* p) {
    uint32_t a;
    asm("{ .reg .u64 t; cvta.to.shared.u64 t, %1; cvt.u32.u64 %0, t; }"
        : "=r"(a) : "l"(p));
    return a;
}
__device__ __forceinline__ uint32_t mapa_peer(uint32_t la, uint32_t peer) {
    uint32_t r;
    asm("mapa.shared::cluster.u32 %0, %1, %2;" : "=r"(r) : "r"(la), "r"(peer));
    return r;
}
__device__ __forceinline__ void st_remote_f32(uint32_t ra, float v) {
    asm volatile("st.shared::cluster.f32 [%0], %1;" :: "r"(ra), "f"(v) : "memory");
}
__device__ __forceinline__ void arrive_remote(uint32_t ra) {
    asm volatile("mbarrier.arrive.release.cluster.shared::cluster.b64 _, [%0];"
                 :: "r"(ra) : "memory");
}
__device__ __forceinline__ void mbar_wait0(uint32_t a) {
    uint32_t done;
    uint32_t parity = 0;
    do {
        asm volatile(
            "{\n\t.reg .pred p;\n\t"
            "mbarrier.try_wait.parity.acquire.cluster.shared::cta.b64 p, [%1], %2, 0x989680;\n\t"
            "selp.b32 %0, 1, 0, p;\n\t}"
            : "=r"(done) : "r"(a), "r"(parity) : "memory");
    } while (!done);
}
#define CLUSTER_SYNC() do { \
    asm volatile("barrier.cluster.arrive.aligned;" ::: "memory"); \
    asm volatile("barrier.cluster.wait.aligned;"   ::: "memory"); \
} while (0)

// ---- packed f32x2 helpers ----
__device__ __forceinline__ u64 pack2(float lo, float hi) {
    u64 r; asm("mov.b64 %0, {%1, %2};" : "=l"(r) : "f"(lo), "f"(hi)); return r;
}
__device__ __forceinline__ void unpack2(u64 v, float& lo, float& hi) {
    asm("mov.b64 {%0, %1}, %2;" : "=f"(lo), "=f"(hi) : "l"(v));
}
__device__ __forceinline__ u64 fma2(u64 a, u64 b, u64 c) {
    u64 r; asm("fma.rn.f32x2 %0, %1, %2, %3;" : "=l"(r) : "l"(a), "l"(b), "l"(c)); return r;
}

// packed node term: acc2[v] accumulates columns (q*JT+2v, q*JT+2v+1)
template<int IN, int OUT, int JT>
__device__ __forceinline__ void nodeterm2(const float* __restrict__ S, int off,
                                          const float* __restrict__ Ws,
                                          u64* __restrict__ acc2, int n, int q) {
    const int j0 = q * JT;
    #pragma unroll
    for (int v = 0; v < JT / 2; v++) acc2[v] = 0ull;
    const float* srow = S + n * STRIDE + off;
    for (int k = 0; k < IN; k++) {
        float a = srow[k];
        u64 aa = pack2(a, a);
        if constexpr (JT == 8) {
            const ulonglong2* wr = reinterpret_cast<const ulonglong2*>(Ws + k * OUT + j0);
            ulonglong2 w0 = wr[0], w1 = wr[1];
            acc2[0] = fma2(aa, w0.x, acc2[0]);
            acc2[1] = fma2(aa, w0.y, acc2[1]);
            acc2[2] = fma2(aa, w1.x, acc2[2]);
            acc2[3] = fma2(aa, w1.y, acc2[3]);
        } else if constexpr (JT == 4) {
            const ulonglong2* wr = reinterpret_cast<const ulonglong2*>(Ws + k * OUT + j0);
            ulonglong2 w0 = wr[0];
            acc2[0] = fma2(aa, w0.x, acc2[0]);
            acc2[1] = fma2(aa, w0.y, acc2[1]);
        } else {
            const u64* wr = reinterpret_cast<const u64*>(Ws + k * OUT + j0);
            acc2[0] = fma2(aa, wr[0], acc2[0]);
        }
    }
}

// One GCN layer with push-protocol bp exchange and fused colsum.
// csl       : combined-ready? NO — csl is LOCAL+... csl here is the LOCAL csl of
//             this CTA? It must be the *local* scene partial? No: bp must be
//             computed on the LOCAL colsum; peer contributes its own bp.
template<int IN, int OUT, int JT>
__device__ __forceinline__ void layer_run(
    float* __restrict__ sm, const float* __restrict__ Ssrc, int soff,
    float* __restrict__ D,
    const float* __restrict__ csl, float* __restrict__ cslnext,
    const float* __restrict__ Wb, const float* __restrict__ Wn_,
    const float* __restrict__ bias,
    int bpp_off, int mb_idx,
    int tid, int lane, int n, int q, uint32_t peer, uint32_t smbase)
{
    float* base = sm + S_BASE;
    float bp_keep = 0.f;
    bool writer = false;
    int jw = 0;

    // base-partial on LOCAL colsum; 4 threads per output column.
    if (tid < 4 * OUT) {
        const int j = tid >> 2, p = tid & 3;
        float s = 0.f;
        for (int k = p; k < IN; k += 4) s += csl[k] * Wb[k * OUT + j];
        const unsigned m = (4 * OUT >= 32) ? 0xffffffffu : ((1u << (4 * OUT)) - 1u);
        s += __shfl_xor_sync(m, s, 1);
        s += __shfl_xor_sync(m, s, 2);
        if (p == 0) {
            writer = true; jw = j; bp_keep = s;
            st_remote_f32(mapa_peer(smbase + (uint32_t)(bpp_off + j) * 4u, peer), s);
            arrive_remote(mapa_peer(smbase + (uint32_t)(S_MBAR + 2 * mb_idx) * 4u, peer));
        }
    }

    // node term (independent of scene sums) — overlaps peer's push latency
    u64 acc2[JT / 2];
    nodeterm2<IN, OUT, JT>(Ssrc, soff, Wn_, acc2, n, q);

    // combine: writer == combiner (bp_local in register, peer part via mbarrier)
    if (writer) {
        mbar_wait0(smbase + (uint32_t)(S_MBAR + 2 * mb_idx) * 4u);
        base[jw] = bias[jw] + bp_keep + sm[bpp_off + jw];
    }
    __syncthreads();

    // emit + fused colsum for next layer
    const int j0 = q * JT;
    float r[JT];
    #pragma unroll
    for (int v = 0; v < JT / 2; v++) {
        float lo, hi; unpack2(acc2[v], lo, hi);
        r[2 * v]     = fmaxf(base[j0 + 2 * v]     - lo, 0.f);
        r[2 * v + 1] = fmaxf(base[j0 + 2 * v + 1] - hi, 0.f);
    }
    float* drow = D + n * STRIDE + j0;
    #pragma unroll
    for (int v = 0; v < JT; v++) drow[v] = r[v];
    #pragma unroll
    for (int off = 1; off < 32; off <<= 1) {
        #pragma unroll
        for (int v = 0; v < JT; v++)
            r[v] += __shfl_xor_sync(0xffffffffu, r[v], off);
    }
    if (lane == 0) {
        #pragma unroll
        for (int v = 0; v < JT; v++) atomicAdd(&cslnext[j0 + v], r[v]);
    }
    __syncthreads();
}

__global__ __launch_bounds__(THREADS, 1) __cluster_dims__(2, 1, 1)
void gnn_scene_kernel(const float* __restrict__ obj_info,
                      const float* __restrict__ W1, const float* __restrict__ b1,
                      const float* __restrict__ W2, const float* __restrict__ b2,
                      const float* __restrict__ W3, const float* __restrict__ b3,
                      const float* __restrict__ W4, const float* __restrict__ b4,
                      const float* __restrict__ Wn, const float* __restrict__ bn,
                      const float* __restrict__ Wg1, const float* __restrict__ bg1,
                      const float* __restrict__ Wg2, const float* __restrict__ bg2,
                      float* __restrict__ out) {
    extern __shared__ float sm[];
    const int tid  = threadIdx.x;
    const int lane = tid & 31;
    const int b    = blockIdx.x >> 1;
    const uint32_t rank = blockIdx.x & 1;
    const uint32_t peer = rank ^ 1u;
    const int n = tid & (LOCALN - 1);
    const int q = tid >> 6;
    const uint32_t smbase = smem_u32(sm);

    // ---- mbarrier init (counts = peer writer lanes per exchange) ----
    if (tid == 0) {
        const uint32_t cnts[6] = {64u, 64u, 32u, 16u, 2u, 16u};
        #pragma unroll
        for (int i = 0; i < 6; i++)
            asm volatile("mbarrier.init.shared.b64 [%0], %1;"
                         :: "r"(smbase + (uint32_t)(S_MBAR + 2 * i) * 4u), "r"(cnts[i])
                         : "memory");
    }

    // ---- load + prescale weights ----
    for (int i = tid; i < 5 * 64; i += THREADS) {
        float w = W1[i];
        sm[S_W1s + i]    = w * INV127;
        sm[S_W1s128 + i] = w * (128.0f * INV127);
    }
    #define CPYS(dst, src, cnt) \
        for (int i = tid; i < (cnt); i += THREADS) sm[(dst) + i] = src[i] * INV127;
    #define CPY(dst, src, cnt) \
        for (int i = tid; i < (cnt); i += THREADS) sm[(dst) + i] = src[i];
    CPYS(S_W2s, W2, 75*64);  CPY(S_B2, b2, 64);
    CPYS(S_W3s, W3, 64*32);  CPY(S_B3, b3, 32);
    CPYS(S_W4s, W4, 32*16);  CPY(S_B4, b4, 16);
    CPYS(S_WNs, Wn, 16*2);   CPY(S_BN, bn, 2);
    CPY(S_B1, b1, 64);
    CPY(S_WG1, Wg1, 16*8);   CPY(S_BG1, bg1, 8);
    CPY(S_WG2, Wg2, 8);      CPY(S_BG2, bg2, 1);
    #undef CPYS
    #undef CPY

    // ---- load this CTA's 64 rows of info[b] into A cols 64..74 ----
    {
        const float* src = obj_info + ((size_t)b * NODES + rank * LOCALN) * 11;
        for (int i = tid; i < LOCALN * 11; i += THREADS) {
            int r = i / 11, c = i % 11;
            sm[S_A + r * STRIDE + 64 + c] = src[i];
        }
    }
    // zero atomic-accumulated csl slots: s2[0..63], s3[0..63], s4[0..31], s5[0..15]
    if (tid < 64)                    sm[S_CS2 + tid] = 0.f;
    else if (tid < 128)              sm[S_CS3 + tid - 64] = 0.f;
    else if (tid < 160)              sm[S_CS4 + tid - 128] = 0.f;
    else if (tid < 176)              sm[S_CS5 + tid - 160] = 0.f;
    __syncthreads();
    CLUSTER_SYNC();   // peer mbarriers initialized before any push

    float* A  = sm + S_A;
    float* Bb = sm + S_BUF;

    // ---- info colsum (11 cols x 64 rows) -> s2[64..74] ----
    if (tid < 11 * 16) {
        int c = tid % 11, p = tid / 11;
        float s = 0.f;
        #pragma unroll
        for (int r = 0; r < 4; r++) s += A[(p * 4 + r) * STRIDE + 64 + c];
        sm[S_PART + p * 11 + c] = s;
    }
    __syncthreads();
    if (tid < 11) {
        float s = 0.f;
        #pragma unroll
        for (int p = 0; p < 16; p++) s += sm[S_PART + p * 11 + tid];
        sm[S_CS2 + 64 + tid] = s;
    }
    __syncthreads();

    // L1 (edge): info[:, :5] -> h1 (A cols 0..63); csl-next -> s2[0..63]
    layer_run<5, 64, 8>(sm, A, 64, A, sm + S_CS2 + 64, sm + S_CS2,
                        sm + S_W1s, sm + S_W1s128, sm + S_B1,
                        S_BPP1, 0, tid, lane, n, q, peer, smbase);

    // L2: h75 (A cols 0..74) -> h2 (Bb cols 0..63); csl-next -> s3
    layer_run<75, 64, 8>(sm, A, 0, Bb, sm + S_CS2, sm + S_CS3,
                         sm + S_W2s, sm + S_W2s, sm + S_B2,
                         S_BPP2, 1, tid, lane, n, q, peer, smbase);

    // L3: h2 -> h3 (A cols 0..31); csl-next -> s4
    layer_run<64, 32, 4>(sm, Bb, 0, A, sm + S_CS3, sm + S_CS4,
                         sm + S_W3s, sm + S_W3s, sm + S_B3,
                         S_BPP3, 2, tid, lane, n, q, peer, smbase);

    // L4: h3 -> h4 (Bb cols 0..15); csl-next -> s5
    layer_run<32, 16, 2>(sm, A, 0, Bb, sm + S_CS4, sm + S_CS5,
                         sm + S_W4s, sm + S_W4s, sm + S_B4,
                         S_BPP4, 3, tid, lane, n, q, peer, smbase);

    // ---- scene csl push: rank1 sends its h4 colsum to rank0 ----
    if (rank == 1 && tid < 16) {
        st_remote_f32(mapa_peer(smbase + (uint32_t)(S_SCENEB + tid) * 4u, peer),
                      sm[S_CS5 + tid]);
        arrive_remote(mapa_peer(smbase + (uint32_t)(S_MBAR + 2 * 5) * 4u, peer));
    }

    // ---- node head ----
    {
        float* base = sm + S_BASE;
        float bph = 0.f; bool wh = false; int jh = 0;
        if (tid < 8) {
            int j = tid >> 2, p = tid & 3;
            float s = 0.f;
            for (int k = p; k < 16; k += 4) s += sm[S_CS5 + k] * sm[S_WNs + k * 2 + j];
            s += __shfl_xor_sync(0xffu, s, 1);
            s += __shfl_xor_sync(0xffu, s, 2);
            if (p == 0) {
                wh = true; jh = j; bph = s;
                st_remote_f32(mapa_peer(smbase + (uint32_t)(S_BPPH + j) * 4u, peer), s);
                arrive_remote(mapa_peer(smbase + (uint32_t)(S_MBAR + 2 * 4) * 4u, peer));
            }
        }
        float accn = 0.f;
        if (q < 2) {
            const float* srow = Bb + n * STRIDE;
            #pragma unroll
            for (int k = 0; k < 16; k++) accn += srow[k] * sm[S_WNs + k * 2 + q];
        }
        if (wh) {
            mbar_wait0(smbase + (uint32_t)(S_MBAR + 2 * 4) * 4u);
            base[jh] = sm[S_BN + jh] + bph + sm[S_BPPH + jh];
        }
        __syncthreads();
        if (q < 2) {
            size_t gnode = (size_t)b * NODES + rank * LOCALN + n;
            out[64 + gnode * 2 + q] = base[q] - accn;
        }
    }

    // ---- scene head: rank0 thread 0 ----
    if (rank == 0 && tid == 0) {
        mbar_wait0(smbase + (uint32_t)(S_MBAR + 2 * 5) * 4u);
        float scene[16];
        #pragma unroll
        for (int k = 0; k < 16; k++)
            scene[k] = (sm[S_CS5 + k] + sm[S_SCENEB + k]) * (1.0f / NODES);
        float z = sm[S_BG2];
        #pragma unroll
        for (int o = 0; o < 8; o++) {
            float g = sm[S_BG1 + o];
            #pragma unroll
            for (int k = 0; k < 16; k++) g += scene[k] * sm[S_WG1 + k * 8 + o];
            g = fmaxf(g, 0.f);
            z += g * sm[S_WG2 + o];
        }
        out[b] = 1.0f / (1.0f + expf(-z));
    }

    // no CTA may exit while peer pushes into its smem could be in flight
    CLUSTER_SYNC();
}

extern "C" void kernel_launch(void* const* d_in, const int* in_sizes, int n_in,
                              void* d_out, int out_size) {
    const float* obj = (const float*)d_in[0];
    const float* W1  = (const float*)d_in[1];
    const float* b1  = (const float*)d_in[2];
    const float* W2  = (const float*)d_in[3];
    const float* b2  = (const float*)d_in[4];
    const float* W3  = (const float*)d_in[5];
    const float* b3  = (const float*)d_in[6];
    const float* W4  = (const float*)d_in[7];
    const float* b4  = (const float*)d_in[8];
    const float* Wn  = (const float*)d_in[9];
    const float* bn  = (const float*)d_in[10];
    const float* Wg1 = (const float*)d_in[11];
    const float* bg1 = (const float*)d_in[12];
    const float* Wg2 = (const float*)d_in[13];
    const float* bg2 = (const float*)d_in[14];
    // d_in[15]=src, d_in[16]=dst: complete graph, exploited analytically.

    cudaFuncSetAttribute(gnn_scene_kernel,
                         cudaFuncAttributeMaxDynamicSharedMemorySize, SMEM_BYTES);
    gnn_scene_kernel<<<SCENES * 2, THREADS, SMEM_BYTES>>>(
        obj, W1, b1, W2, b2, W3, b3, W4, b4, Wn, bn, Wg1, bg1, Wg2, bg2,
        (float*)d_out);
}